// round 2
// baseline (speedup 1.0000x reference)
#include <cuda_runtime.h>
#include <math.h>

#define Bb   256
#define Ll   512
#define Ff   28
#define Hh   512
#define G4   2048
#define NBLK 128
#define NTHR 256

// ---------------- scratch ----------------
__device__ float g_xf[Ll * Bb * Ff];      // [l][b][f]
__device__ float g_ua[Ll * Bb];           // [l][b]
__device__ float g_bm[Ll * Bb];           // [l][b]
__device__ float g_uab[Bb * Ll];          // [b][l]
__device__ float g_bmb[Bb * Ll];          // [b][l]
__device__ float g_h[Bb * Hh];
__device__ float g_c[Bb * Hh];
__device__ float g_wapart[Bb * 32];       // [b][ntile]
__device__ float g_fcpart[Ll * Bb * 32];  // [t][b][ntile]
__device__ float g_stats[Ll * 2];         // [l]{m, 1/D}
__device__ float g_ctx[Bb * Ff];          // [b][f]
__device__ float g_wpack[G4 * Hh];
__device__ unsigned g_cnt = 0;
__device__ volatile unsigned g_gen = 0;

__device__ __forceinline__ void grid_barrier() {
    __syncthreads();
    if (threadIdx.x == 0) {
        __threadfence();
        unsigned gen = g_gen;
        if (atomicAdd(&g_cnt, 1u) == NBLK - 1) {
            g_cnt = 0;
            __threadfence();
            g_gen = gen + 1;
        } else {
            while (g_gen == gen) { __nanosleep(20); }
            __threadfence();
        }
    }
    __syncthreads();
}

__device__ __forceinline__ float sigm(float x) { return 1.f / (1.f + __expf(-x)); }

// wpack[((nt*512 + k)*16 + nri)*4 + q] = W_hh[(q*512 + nt*16 + nri)*512 + k]
__global__ void pack_whh(const float* __restrict__ whh) {
    int o = blockIdx.x * blockDim.x + threadIdx.x;
    if (o >= G4 * Hh) return;
    int q = o & 3, nri = (o >> 2) & 15, k = (o >> 6) & 511, nt = o >> 15;
    g_wpack[o] = whh[(q * Hh + nt * 16 + nri) * Hh + k];
}

__global__ void prep(const float* __restrict__ x, const float* __restrict__ mask,
                     const float* __restrict__ w1, const float* __restrict__ b1,
                     const float* __restrict__ cw, const float* __restrict__ cb) {
    __shared__ float w1s[Ff * Ff * 3];
    __shared__ float cws[Ff];
    for (int i = threadIdx.x; i < Ff * Ff * 3; i += blockDim.x) w1s[i] = w1[i];
    if (threadIdx.x < Ff) cws[threadIdx.x] = cw[threadIdx.x];
    __syncthreads();
    int gid = blockIdx.x * blockDim.x + threadIdx.x;
    int b = gid / Ll, l = gid % Ll;
    float m = mask[b * Ll + l];
    const float* xrow = x + (size_t)(b * Ll + l) * Ff;
    float accu = 0.f;
    for (int fo = 0; fo < Ff; fo++) {
        float a = b1[fo];
        #pragma unroll
        for (int k = 0; k < 3; k++) {
            int ll = l - 1 + k;
            if (ll >= 0 && ll < Ll) {
                const float* xp = x + (size_t)(b * Ll + ll) * Ff;
                const float* wp = w1s + fo * (Ff * 3) + k;
                #pragma unroll 7
                for (int fi = 0; fi < Ff; fi++) a += xp[fi] * wp[fi * 3];
            }
        }
        a *= m;
        a = (a > 0.f) ? a : (expf(a) - 1.f);   // elu
        float xfv = a + xrow[fo];
        g_xf[(l * Bb + b) * Ff + fo] = xfv;
        accu += xfv * cws[fo];
    }
    float ua = accu + cb[0];
    float bm = 1e9f * (m - 1.f);
    g_ua[l * Bb + b] = ua;  g_uab[b * Ll + l] = ua;
    g_bm[l * Bb + b] = bm;  g_bmb[b * Ll + l] = bm;
}

__device__ __forceinline__ void gemm_chunk(int kc0, int b0, int nt, int tid, int tx, int ty,
                                           float (&acc)[4][4], float* hs, float* ws) {
    __syncthreads();
    #pragma unroll
    for (int r = 0; r < 2; r++) {
        int i4 = tid + r * NTHR;
        int bb = i4 >> 3, c4 = i4 & 7;
        *(float4*)&hs[bb * 36 + c4 * 4] =
            *(const float4*)&g_h[(b0 + bb) * Hh + kc0 + c4 * 4];
        *(float4*)&ws[i4 * 4] =
            *(const float4*)&g_wpack[(nt * Hh + kc0) * 64 + i4 * 4];
    }
    __syncthreads();
    #pragma unroll
    for (int k = 0; k < 32; k++) {
        float4 wv = *(float4*)&ws[k * 64 + tx * 4];
        float h0 = hs[(ty * 4 + 0) * 36 + k];
        float h1 = hs[(ty * 4 + 1) * 36 + k];
        float h2 = hs[(ty * 4 + 2) * 36 + k];
        float h3 = hs[(ty * 4 + 3) * 36 + k];
        acc[0][0] += h0 * wv.x; acc[0][1] += h0 * wv.y; acc[0][2] += h0 * wv.z; acc[0][3] += h0 * wv.w;
        acc[1][0] += h1 * wv.x; acc[1][1] += h1 * wv.y; acc[1][2] += h1 * wv.z; acc[1][3] += h1 * wv.w;
        acc[2][0] += h2 * wv.x; acc[2][1] += h2 * wv.y; acc[2][2] += h2 * wv.z; acc[2][3] += h2 * wv.w;
        acc[3][0] += h3 * wv.x; acc[3][1] += h3 * wv.y; acc[3][2] += h3 * wv.z; acc[3][3] += h3 * wv.w;
    }
}

__global__ void __launch_bounds__(NTHR, 1) scan(
    const float* __restrict__ fc1w, const float* __restrict__ fc1b,
    const float* __restrict__ wih,  const float* __restrict__ bih,
    const float* __restrict__ bhh,  const float* __restrict__ w2) {

    __shared__ __align__(16) float hs[64 * 36];
    __shared__ __align__(16) float ws[32 * 64];
    __shared__ float wa_s[Bb];
    __shared__ float red[64 * 16];
    __shared__ float ctx_s[64 * Ff];
    __shared__ float wih_s[64 * 29];   // [(q*16+tx)*29 + f]
    __shared__ float bsum_s[64];       // [q*16+tx]
    __shared__ float ctxacc[2 * 4 * Ff];
    __shared__ float stm[8], stdd[8];

    const int tid = threadIdx.x;
    const int blk = blockIdx.x;
    const int bt = blk >> 5, nt = blk & 31;
    const int b0 = bt * 64, n0 = nt * 16;
    const int tx = tid & 15, ty = tid >> 4;
    const int n = n0 + tx;

    const float f1n = fc1w[n];
    const float w2n = w2[n];
    const float f1b0 = fc1b[0];

    for (int i = tid; i < 64 * Ff; i += NTHR) {
        int r = i / Ff, f = i % Ff;          // r = q*16 + txr
        int row = (r >> 4) * Hh + n0 + (r & 15);
        wih_s[r * 29 + f] = wih[row * Ff + f];
    }
    if (tid < 64) {
        int row = (tid >> 4) * Hh + n0 + (tid & 15);
        bsum_s[tid] = bih[row] + bhh[row];
    }

    for (int i = blk * NTHR + tid; i < Bb * Hh; i += NBLK * NTHR) { g_h[i] = 0.f; g_c[i] = 0.f; }
    for (int i = blk * NTHR + tid; i < Bb * 32; i += NBLK * NTHR) g_wapart[i] = 0.f;
    grid_barrier();

    float acc[4][4];
    #pragma unroll
    for (int i = 0; i < 4; i++)
        #pragma unroll
        for (int j = 0; j < 4; j++) acc[i][j] = 0.f;

    for (int t = 0; t < Ll; t++) {
        // ---- PHASE A: w_a reduce + softmax stats + GEMM 0-7 ----
        {
            float s = 0.f;
            const float* wp = g_wapart + tid * 32;
            #pragma unroll
            for (int j = 0; j < 32; j++) s += wp[j];
            wa_s[tid] = s + f1b0;
        }
        __syncthreads();
        {
            int lq = tid >> 6, tsub = tid & 63;
            int l = blk * 4 + lq;
            float mx = -1e30f, dd = 0.f;
            #pragma unroll
            for (int r = 0; r < 4; r++) {
                int b = tsub + r * 64;
                float s = g_ua[l * Bb + b] + wa_s[b];
                s = (s > 0.f) ? s : 0.01f * s;
                s += g_bm[l * Bb + b];
                float mn = fmaxf(mx, s);
                dd = dd * __expf(mx - mn) + __expf(s - mn);
                mx = mn;
            }
            #pragma unroll
            for (int off = 16; off; off >>= 1) {
                float mo = __shfl_down_sync(0xffffffffu, mx, off);
                float d2 = __shfl_down_sync(0xffffffffu, dd, off);
                float mn = fmaxf(mx, mo);
                dd = dd * __expf(mx - mn) + d2 * __expf(mo - mn);
                mx = mn;
            }
            if ((tid & 31) == 0) { stm[tid >> 5] = mx; stdd[tid >> 5] = dd; }
        }
        __syncthreads();
        if (tid < 4) {
            float m1 = stm[tid * 2], d1 = stdd[tid * 2];
            float m2 = stm[tid * 2 + 1], d2 = stdd[tid * 2 + 1];
            float mn = fmaxf(m1, m2);
            float dd = d1 * __expf(m1 - mn) + d2 * __expf(m2 - mn);
            int l = blk * 4 + tid;
            g_stats[l * 2] = mn;
            g_stats[l * 2 + 1] = 1.f / dd;
        }
        for (int ch = 0; ch < 8; ch++) gemm_chunk(ch * 32, b0, nt, tid, tx, ty, acc, hs, ws);
        grid_barrier();

        // ---- PHASE B: context + GEMM 8-15 ----
        {
            int w = tid >> 5, lane = tid & 31;
            int bloc = w >> 2, q4 = w & 3;
            int b = blk * 2 + bloc;
            float wab = wa_s[b];
            float accf = 0.f;
            for (int lg = q4 * 128; lg < q4 * 128 + 128; lg += 32) {
                int lme = lg + lane;
                float su = g_uab[b * Ll + lme] + wab;
                su = (su > 0.f) ? su : 0.01f * su;
                su += g_bmb[b * Ll + lme];
                float p = __expf(su - g_stats[lme * 2]) * g_stats[lme * 2 + 1];
                #pragma unroll
                for (int j = 0; j < 32; j++) {
                    float pj = __shfl_sync(0xffffffffu, p, j);
                    if (lane < Ff)
                        accf += pj * g_xf[((lg + j) * Bb + b) * Ff + lane];
                }
            }
            if (lane < Ff) ctxacc[(bloc * 4 + q4) * Ff + lane] = accf;
        }
        __syncthreads();
        if (tid < 2 * Ff) {
            int bloc = tid / Ff, f = tid % Ff;
            float s = 0.f;
            #pragma unroll
            for (int q4 = 0; q4 < 4; q4++) s += ctxacc[(bloc * 4 + q4) * Ff + f];
            g_ctx[(blk * 2 + bloc) * Ff + f] = s;
        }
        for (int ch = 8; ch < 16; ch++) gemm_chunk(ch * 32, b0, nt, tid, tx, ty, acc, hs, ws);
        grid_barrier();

        // ---- PHASE C: epilogue + LSTM pointwise ----
        for (int i = tid; i < 64 * Ff; i += NTHR) ctx_s[i] = g_ctx[b0 * Ff + i];
        __syncthreads();
        float hnv[4];
        #pragma unroll
        for (int bi = 0; bi < 4; bi++) {
            int bl = ty * 4 + bi;
            const float* cp = ctx_s + bl * Ff;
            float d0 = 0.f, d1 = 0.f, d2 = 0.f, d3 = 0.f;
            #pragma unroll
            for (int fI = 0; fI < Ff; fI++) {
                float cv = cp[fI];
                d0 += cv * wih_s[(0 * 16 + tx) * 29 + fI];
                d1 += cv * wih_s[(1 * 16 + tx) * 29 + fI];
                d2 += cv * wih_s[(2 * 16 + tx) * 29 + fI];
                d3 += cv * wih_s[(3 * 16 + tx) * 29 + fI];
            }
            float gi = acc[bi][0] + d0 + bsum_s[0 * 16 + tx];
            float gf = acc[bi][1] + d1 + bsum_s[1 * 16 + tx];
            float gg = acc[bi][2] + d2 + bsum_s[2 * 16 + tx];
            float go = acc[bi][3] + d3 + bsum_s[3 * 16 + tx];
            int bg = b0 + bl;
            float co = g_c[bg * Hh + n];
            float cn = sigm(gf) * co + sigm(gi) * tanhf(gg);
            float hn = sigm(go) * tanhf(cn);
            g_c[bg * Hh + n] = cn;
            g_h[bg * Hh + n] = hn;
            hnv[bi] = hn;
            acc[bi][0] = acc[bi][1] = acc[bi][2] = acc[bi][3] = 0.f;
        }
        #pragma unroll
        for (int bi = 0; bi < 4; bi++) red[(ty * 4 + bi) * 16 + tx] = hnv[bi] * f1n;
        __syncthreads();
        if (tid < 64) {
            float s = 0.f;
            #pragma unroll
            for (int j = 0; j < 16; j++) s += red[tid * 16 + j];
            g_wapart[(b0 + tid) * 32 + nt] = s;
        }
        __syncthreads();
        #pragma unroll
        for (int bi = 0; bi < 4; bi++) red[(ty * 4 + bi) * 16 + tx] = hnv[bi] * w2n;
        __syncthreads();
        if (tid < 64) {
            float s = 0.f;
            #pragma unroll
            for (int j = 0; j < 16; j++) s += red[tid * 16 + j];
            g_fcpart[(t * Bb + b0 + tid) * 32 + nt] = s;
        }
        grid_barrier();
    }
}

__global__ void final_out(const float* __restrict__ x, const float* __restrict__ mask,
                          const float* __restrict__ w2, const float* __restrict__ b2,
                          float* __restrict__ out) {
    __shared__ float w2s[Ff];
    if (threadIdx.x < Ff) w2s[threadIdx.x] = w2[Hh + threadIdx.x];
    __syncthreads();
    int gid = blockIdx.x * blockDim.x + threadIdx.x;
    int b = gid / Ll, l = gid % Ll;
    const float* fp = g_fcpart + (size_t)(l * Bb + b) * 32;
    float s = 0.f;
    #pragma unroll
    for (int j = 0; j < 32; j++) s += fp[j];
    float m = mask[b * Ll + l];
    s *= m;
    const float* xr = x + (size_t)(b * Ll + l) * Ff;
    #pragma unroll 7
    for (int f = 0; f < Ff; f++) s += xr[f] * w2s[f];
    out[b * Ll + l] = (s + b2[0]) * m;
}

extern "C" void kernel_launch(void* const* d_in, const int* in_sizes, int n_in,
                              void* d_out, int out_size) {
    const float* x      = (const float*)d_in[0];
    const float* mask   = (const float*)d_in[1];
    const float* conv1w = (const float*)d_in[2];
    const float* conv1b = (const float*)d_in[3];
    const float* convw  = (const float*)d_in[4];
    const float* convb  = (const float*)d_in[5];
    const float* conv2w = (const float*)d_in[6];
    const float* conv2b = (const float*)d_in[7];
    const float* wih    = (const float*)d_in[8];
    const float* whh    = (const float*)d_in[9];
    const float* bih    = (const float*)d_in[10];
    const float* bhh    = (const float*)d_in[11];
    const float* fc1w   = (const float*)d_in[12];
    const float* fc1b   = (const float*)d_in[13];
    float* out = (float*)d_out;

    pack_whh<<<(G4 * Hh + 255) / 256, 256>>>(whh);
    prep<<<(Bb * Ll) / 256, 256>>>(x, mask, conv1w, conv1b, convw, convb);
    scan<<<NBLK, NTHR>>>(fc1w, fc1b, wih, bih, bhh, conv2w);
    final_out<<<(Bb * Ll) / 256, 256>>>(x, mask, conv2w, conv2b, out);
}